// round 1
// baseline (speedup 1.0000x reference)
#include <cuda_runtime.h>
#include <math.h>

#define DMODEL 1024
#define SEQ    2048
#define BATCH  2
#define NHEADS 16
#define HDIM   64
#define MTOK   (BATCH*SEQ)   // 4096
#define DFF    (4*DMODEL)    // 4096
#define LN_EPS 1e-9f

// ---------------- scratch (device globals: allocation-free) ----------------
__device__ float g_ln [MTOK*DMODEL];
__device__ float g_q  [MTOK*DMODEL];
__device__ float g_k  [MTOK*DMODEL];
__device__ float g_v  [MTOK*DMODEL];
__device__ float g_pre[MTOK*DMODEL];
__device__ float g_x1 [MTOK*DMODEL];
__device__ float g_mid[MTOK*DFF];

// ---------------- LayerNorm (ddof=1, eps inside sqrt) ----------------
__global__ void __launch_bounds__(256) ln_kernel(
    const float* __restrict__ x,
    const float* __restrict__ msc,
    const float* __restrict__ ssc,
    float* __restrict__ out)
{
    __shared__ float xs[DMODEL];
    __shared__ float rs[16];
    int row = blockIdx.x;
    const float* xr = x + (size_t)row * DMODEL;
    float s = 0.f, s2 = 0.f;
    #pragma unroll
    for (int i = threadIdx.x; i < DMODEL; i += 256) {
        float v = xr[i]; xs[i] = v; s += v; s2 += v * v;
    }
    #pragma unroll
    for (int o = 16; o > 0; o >>= 1) {
        s  += __shfl_down_sync(0xffffffffu, s,  o);
        s2 += __shfl_down_sync(0xffffffffu, s2, o);
    }
    int wid = threadIdx.x >> 5;
    if ((threadIdx.x & 31) == 0) { rs[wid] = s; rs[8 + wid] = s2; }
    __syncthreads();
    s = 0.f; s2 = 0.f;
    #pragma unroll
    for (int w = 0; w < 8; w++) { s += rs[w]; s2 += rs[8 + w]; }
    float mean = s * (1.f / DMODEL);
    float var  = (s2 - (float)DMODEL * mean * mean) * (1.f / (DMODEL - 1));
    float inv  = rsqrtf(var + LN_EPS);
    float* outr = out + (size_t)row * DMODEL;
    #pragma unroll
    for (int i = threadIdx.x; i < DMODEL; i += 256)
        outr[i] = (xs[i] - mean) * inv * ssc[i] + msc[i];
}

// ---------------- SGEMM  C = A(MxK) * W(NxK)^T  [+Res] [+GELU] ----------------
__device__ __forceinline__ float gelu_exact(float x) {
    return 0.5f * x * (1.f + erff(x * 0.70710678118654752f));
}

template<int GELU>
__global__ void __launch_bounds__(256) gemm_nt_kernel(
    const float* __restrict__ A, const float* __restrict__ W,
    const float* __restrict__ Res, float* __restrict__ C,
    int M, int N, int K)
{
    const int BM = 128, BN = 128, BK = 16;
    __shared__ float As[BK][BM + 4];
    __shared__ float Bs[BK][BN + 4];
    int bm = blockIdx.y * BM, bn = blockIdx.x * BN;
    int tid = threadIdx.x;
    int tx = tid & 15, ty = tid >> 4;      // tx -> n dir, ty -> m dir
    int lrow = tid >> 2;                   // 0..63
    int lcol = (tid & 3) << 2;             // 0,4,8,12

    float acc[8][8];
    #pragma unroll
    for (int i = 0; i < 8; i++)
        #pragma unroll
        for (int j = 0; j < 8; j++) acc[i][j] = 0.f;

    const float* Ab = A + (size_t)bm * K;
    const float* Wb = W + (size_t)bn * K;

    for (int kb = 0; kb < K; kb += BK) {
        #pragma unroll
        for (int half = 0; half < 2; half++) {
            int r = lrow + half * 64;
            float4 av = *(const float4*)(Ab + (size_t)r * K + kb + lcol);
            As[lcol + 0][r] = av.x; As[lcol + 1][r] = av.y;
            As[lcol + 2][r] = av.z; As[lcol + 3][r] = av.w;
            float4 bv = *(const float4*)(Wb + (size_t)r * K + kb + lcol);
            Bs[lcol + 0][r] = bv.x; Bs[lcol + 1][r] = bv.y;
            Bs[lcol + 2][r] = bv.z; Bs[lcol + 3][r] = bv.w;
        }
        __syncthreads();
        #pragma unroll
        for (int k = 0; k < BK; k++) {
            float a[8], b[8];
            *(float4*)(a)     = *(const float4*)&As[k][ty * 8];
            *(float4*)(a + 4) = *(const float4*)&As[k][ty * 8 + 4];
            *(float4*)(b)     = *(const float4*)&Bs[k][tx * 8];
            *(float4*)(b + 4) = *(const float4*)&Bs[k][tx * 8 + 4];
            #pragma unroll
            for (int i = 0; i < 8; i++)
                #pragma unroll
                for (int j = 0; j < 8; j++)
                    acc[i][j] += a[i] * b[j];
        }
        __syncthreads();
    }

    #pragma unroll
    for (int i = 0; i < 8; i++) {
        int m = bm + ty * 8 + i;
        #pragma unroll
        for (int j4 = 0; j4 < 2; j4++) {
            int n = bn + tx * 8 + j4 * 4;
            float4 v;
            v.x = acc[i][j4 * 4 + 0]; v.y = acc[i][j4 * 4 + 1];
            v.z = acc[i][j4 * 4 + 2]; v.w = acc[i][j4 * 4 + 3];
            if (Res) {
                float4 rr = *(const float4*)(Res + (size_t)m * N + n);
                v.x += rr.x; v.y += rr.y; v.z += rr.z; v.w += rr.w;
            }
            if (GELU) {
                v.x = gelu_exact(v.x); v.y = gelu_exact(v.y);
                v.z = gelu_exact(v.z); v.w = gelu_exact(v.w);
            }
            *(float4*)(C + (size_t)m * N + n) = v;
        }
    }
}

// ---------------- Flash attention (fp32, causal) ----------------
// Grid: (qtiles=32, B*H=32), 64 threads, one query row per thread.
__global__ void __launch_bounds__(64) attn_kernel(
    const float* __restrict__ Q, const float* __restrict__ K,
    const float* __restrict__ V, float* __restrict__ O)
{
    __shared__ float Qs[64][64];
    __shared__ float Ks[64][64];
    __shared__ float Vs[64][64];

    int qt = gridDim.x - 1 - blockIdx.x;   // heavy tiles first
    int bh = blockIdx.y;
    int b = bh / NHEADS, h = bh % NHEADS;
    int r = threadIdx.x;
    int sq = qt * 64 + r;

    const float* Qp = Q + (size_t)b * SEQ * DMODEL + h * HDIM;
    const float* Kp = K + (size_t)b * SEQ * DMODEL + h * HDIM;
    const float* Vp = V + (size_t)b * SEQ * DMODEL + h * HDIM;
    float*       Op = O + (size_t)b * SEQ * DMODEL + h * HDIM;

    // cooperative, coalesced Q-tile load (scaled by 1/sqrt(hd))
    #pragma unroll 8
    for (int t = 0; t < 64; t++)
        Qs[t][r] = Qp[(size_t)(qt * 64 + t) * DMODEL + r] * 0.125f;
    __syncthreads();

    float q[64];
    #pragma unroll
    for (int d = 0; d < 64; d++) q[d] = Qs[r][d];

    float o[64];
    #pragma unroll
    for (int d = 0; d < 64; d++) o[d] = 0.f;
    float mrun = -INFINITY, lrun = 0.f;

    for (int kt = 0; kt <= qt; kt++) {
        __syncthreads();
        #pragma unroll 8
        for (int t = 0; t < 64; t++) {
            size_t idx = (size_t)(kt * 64 + t) * DMODEL + r;
            Ks[t][r] = Kp[idx];
            Vs[t][r] = Vp[idx];
        }
        __syncthreads();

        bool diag = (kt == qt);
        for (int h2 = 0; h2 < 2; h2++) {
            float s[32];
            #pragma unroll
            for (int kk = 0; kk < 32; kk++) {
                float acc = 0.f;
                #pragma unroll
                for (int d4 = 0; d4 < 16; d4++) {
                    float4 kv = *(const float4*)&Ks[h2 * 32 + kk][d4 * 4];
                    acc += q[d4 * 4 + 0] * kv.x;
                    acc += q[d4 * 4 + 1] * kv.y;
                    acc += q[d4 * 4 + 2] * kv.z;
                    acc += q[d4 * 4 + 3] * kv.w;
                }
                s[kk] = acc;
            }
            if (diag) {
                #pragma unroll
                for (int kk = 0; kk < 32; kk++)
                    if (h2 * 32 + kk > r) s[kk] = -INFINITY;
            }
            float mt = mrun;
            #pragma unroll
            for (int kk = 0; kk < 32; kk++) mt = fmaxf(mt, s[kk]);
            float corr = __expf(mrun - mt);
            lrun *= corr;
            #pragma unroll
            for (int d = 0; d < 64; d++) o[d] *= corr;
            #pragma unroll
            for (int kk = 0; kk < 32; kk++) {
                float p = __expf(s[kk] - mt);
                lrun += p;
                s[kk] = p;
            }
            #pragma unroll
            for (int kk = 0; kk < 32; kk++) {
                float p = s[kk];
                #pragma unroll
                for (int d4 = 0; d4 < 16; d4++) {
                    float4 vv = *(const float4*)&Vs[h2 * 32 + kk][d4 * 4];
                    o[d4 * 4 + 0] += p * vv.x;
                    o[d4 * 4 + 1] += p * vv.y;
                    o[d4 * 4 + 2] += p * vv.z;
                    o[d4 * 4 + 3] += p * vv.w;
                }
            }
            mrun = mt;
        }
    }

    float inv = 1.f / lrun;
    float* outp = Op + (size_t)sq * DMODEL;
    #pragma unroll
    for (int d4 = 0; d4 < 16; d4++) {
        float4 v;
        v.x = o[d4 * 4 + 0] * inv; v.y = o[d4 * 4 + 1] * inv;
        v.z = o[d4 * 4 + 2] * inv; v.w = o[d4 * 4 + 3] * inv;
        *(float4*)(outp + d4 * 4) = v;
    }
}

// ---------------- launch ----------------
extern "C" void kernel_launch(void* const* d_in, const int* in_sizes, int n_in,
                              void* d_out, int out_size)
{
    const float* x     = (const float*)d_in[0];
    const float* Wq    = (const float*)d_in[1];
    const float* Wk    = (const float*)d_in[2];
    const float* Wv    = (const float*)d_in[3];
    const float* Wo    = (const float*)d_in[4];
    const float* Wup   = (const float*)d_in[5];
    const float* Wdown = (const float*)d_in[6];
    const float* ln1m  = (const float*)d_in[7];
    const float* ln1s  = (const float*)d_in[8];
    const float* ln2m  = (const float*)d_in[9];
    const float* ln2s  = (const float*)d_in[10];
    float* out = (float*)d_out;

    float *ln, *q, *k, *v, *pre, *x1, *mid;
    cudaGetSymbolAddress((void**)&ln,  g_ln);
    cudaGetSymbolAddress((void**)&q,   g_q);
    cudaGetSymbolAddress((void**)&k,   g_k);
    cudaGetSymbolAddress((void**)&v,   g_v);
    cudaGetSymbolAddress((void**)&pre, g_pre);
    cudaGetSymbolAddress((void**)&x1,  g_x1);
    cudaGetSymbolAddress((void**)&mid, g_mid);

    // LN1
    ln_kernel<<<MTOK, 256>>>(x, ln1m, ln1s, ln);

    // Q, K, V projections
    dim3 gD(DMODEL / 128, MTOK / 128);
    gemm_nt_kernel<0><<<gD, 256>>>(ln, Wq, nullptr, q, MTOK, DMODEL, DMODEL);
    gemm_nt_kernel<0><<<gD, 256>>>(ln, Wk, nullptr, k, MTOK, DMODEL, DMODEL);
    gemm_nt_kernel<0><<<gD, 256>>>(ln, Wv, nullptr, v, MTOK, DMODEL, DMODEL);

    // causal flash attention
    attn_kernel<<<dim3(SEQ / 64, BATCH * NHEADS), 64>>>(q, k, v, pre);

    // output projection + residual (x1 = x + attn_out)
    gemm_nt_kernel<0><<<gD, 256>>>(pre, Wo, x, x1, MTOK, DMODEL, DMODEL);

    // LN2
    ln_kernel<<<MTOK, 256>>>(x1, ln2m, ln2s, ln);

    // MLP up + exact GELU
    dim3 gUp(DFF / 128, MTOK / 128);
    gemm_nt_kernel<1><<<gUp, 256>>>(ln, Wup, nullptr, mid, MTOK, DFF, DMODEL);

    // MLP down + residual -> output
    gemm_nt_kernel<0><<<gD, 256>>>(mid, Wdown, x1, out, MTOK, DMODEL, DFF);
}

// round 2
// speedup vs baseline: 1.6173x; 1.6173x over previous
#include <cuda_runtime.h>
#include <math.h>

#define DMODEL 1024
#define SEQ    2048
#define BATCH  2
#define NHEADS 16
#define HDIM   64
#define MTOK   (BATCH*SEQ)   // 4096
#define DFF    (4*DMODEL)    // 4096
#define LN_EPS 1e-9f

// ---------------- scratch (device globals: allocation-free) ----------------
__device__ float g_ln [MTOK*DMODEL];
__device__ float g_q  [MTOK*DMODEL];
__device__ float g_k  [MTOK*DMODEL];
__device__ float g_v  [MTOK*DMODEL];
__device__ float g_pre[MTOK*DMODEL];
__device__ float g_x1 [MTOK*DMODEL];
__device__ float g_mid[MTOK*DFF];

// ---------------- LayerNorm (ddof=1, eps inside sqrt) ----------------
__global__ void __launch_bounds__(256) ln_kernel(
    const float* __restrict__ x,
    const float* __restrict__ msc,
    const float* __restrict__ ssc,
    float* __restrict__ out)
{
    __shared__ float xs[DMODEL];
    __shared__ float rs[16];
    int row = blockIdx.x;
    const float* xr = x + (size_t)row * DMODEL;
    float s = 0.f, s2 = 0.f;
    #pragma unroll
    for (int i = threadIdx.x; i < DMODEL; i += 256) {
        float v = xr[i]; xs[i] = v; s += v; s2 += v * v;
    }
    #pragma unroll
    for (int o = 16; o > 0; o >>= 1) {
        s  += __shfl_down_sync(0xffffffffu, s,  o);
        s2 += __shfl_down_sync(0xffffffffu, s2, o);
    }
    int wid = threadIdx.x >> 5;
    if ((threadIdx.x & 31) == 0) { rs[wid] = s; rs[8 + wid] = s2; }
    __syncthreads();
    s = 0.f; s2 = 0.f;
    #pragma unroll
    for (int w = 0; w < 8; w++) { s += rs[w]; s2 += rs[8 + w]; }
    float mean = s * (1.f / DMODEL);
    float var  = (s2 - (float)DMODEL * mean * mean) * (1.f / (DMODEL - 1));
    float inv  = rsqrtf(var + LN_EPS);
    float* outr = out + (size_t)row * DMODEL;
    #pragma unroll
    for (int i = threadIdx.x; i < DMODEL; i += 256)
        outr[i] = (xs[i] - mean) * inv * ssc[i] + msc[i];
}

// ---------------- helpers ----------------
__device__ __forceinline__ float gelu_exact(float x) {
    return 0.5f * x * (1.f + erff(x * 0.70710678118654752f));
}
__device__ __forceinline__ unsigned f2tf32(float f) {
    unsigned u;
    asm("cvt.rna.tf32.f32 %0, %1;" : "=r"(u) : "f"(f));
    return u;
}
__device__ __forceinline__ void mma_tf32(float c[4],
    unsigned a0, unsigned a1, unsigned a2, unsigned a3,
    unsigned b0, unsigned b1)
{
    asm volatile(
        "mma.sync.aligned.m16n8k8.row.col.f32.tf32.tf32.f32 "
        "{%0,%1,%2,%3}, {%4,%5,%6,%7}, {%8,%9}, {%0,%1,%2,%3};\n"
        : "+f"(c[0]), "+f"(c[1]), "+f"(c[2]), "+f"(c[3])
        : "r"(a0), "r"(a1), "r"(a2), "r"(a3), "r"(b0), "r"(b1));
}

// ---------------- TF32 tensor-core GEMM  C = A(MxK) * W(NxK)^T [+Res][+GELU] --
// 128x128x32 CTA tile, 8 warps, each warp 64x32 via 4x4 grid of m16n8k8 mmas.
// smem stride 36 floats -> fragment LDS bank-conflict-free.
template<int GELU>
__global__ void __launch_bounds__(256, 2) gemm_tf32_kernel(
    const float* __restrict__ A, const float* __restrict__ W,
    const float* __restrict__ Res, float* __restrict__ C,
    int M, int N, int K)
{
    const int BM = 128, BN = 128, BK = 32, BKP = 36;
    __shared__ unsigned As[BM * BKP];
    __shared__ unsigned Bs[BN * BKP];

    int bm = blockIdx.y * BM, bn = blockIdx.x * BN;
    int tid = threadIdx.x, lane = tid & 31, wid = tid >> 5;
    int m_base = (wid & 1) * 64;     // 2 warps along M
    int n_base = (wid >> 1) * 32;    // 4 warps along N

    // global->smem: each thread loads 16 consecutive k of one row (A and B)
    int lr = tid >> 1;               // 0..127
    int lk = (tid & 1) * 16;         // 0 or 16
    const float* Ag = A + (size_t)(bm + lr) * K + lk;
    const float* Wg = W + (size_t)(bn + lr) * K + lk;
    unsigned* AsW = As + lr * BKP + lk;
    unsigned* BsW = Bs + lr * BKP + lk;

    float acc[4][4][4];
    #pragma unroll
    for (int mt = 0; mt < 4; mt++)
        #pragma unroll
        for (int nt = 0; nt < 4; nt++)
            #pragma unroll
            for (int e = 0; e < 4; e++) acc[mt][nt][e] = 0.f;

    int fr = lane >> 2, fc = lane & 3;   // fragment row/col within 8x4 group

    for (int kb = 0; kb < K; kb += BK) {
        #pragma unroll
        for (int i = 0; i < 4; i++) {
            float4 av = *(const float4*)(Ag + kb + i * 4);
            AsW[i * 4 + 0] = f2tf32(av.x); AsW[i * 4 + 1] = f2tf32(av.y);
            AsW[i * 4 + 2] = f2tf32(av.z); AsW[i * 4 + 3] = f2tf32(av.w);
            float4 bv = *(const float4*)(Wg + kb + i * 4);
            BsW[i * 4 + 0] = f2tf32(bv.x); BsW[i * 4 + 1] = f2tf32(bv.y);
            BsW[i * 4 + 2] = f2tf32(bv.z); BsW[i * 4 + 3] = f2tf32(bv.w);
        }
        __syncthreads();

        #pragma unroll
        for (int ks = 0; ks < 4; ks++) {
            int k0 = ks * 8;
            unsigned a[4][4], b[4][2];
            #pragma unroll
            for (int mt = 0; mt < 4; mt++) {
                const unsigned* p = As + (m_base + mt * 16 + fr) * BKP + k0 + fc;
                a[mt][0] = p[0];
                a[mt][1] = p[8 * BKP];
                a[mt][2] = p[4];
                a[mt][3] = p[8 * BKP + 4];
            }
            #pragma unroll
            for (int nt = 0; nt < 4; nt++) {
                const unsigned* p = Bs + (n_base + nt * 8 + fr) * BKP + k0 + fc;
                b[nt][0] = p[0];
                b[nt][1] = p[4];
            }
            #pragma unroll
            for (int mt = 0; mt < 4; mt++)
                #pragma unroll
                for (int nt = 0; nt < 4; nt++)
                    mma_tf32(acc[mt][nt], a[mt][0], a[mt][1], a[mt][2], a[mt][3],
                             b[nt][0], b[nt][1]);
        }
        __syncthreads();
    }

    // epilogue: c0,c1 -> (row, col..col+1); c2,c3 -> (row+8, ...)
    int er = lane >> 2, ec = (lane & 3) * 2;
    #pragma unroll
    for (int mt = 0; mt < 4; mt++) {
        #pragma unroll
        for (int nt = 0; nt < 4; nt++) {
            int row = bm + m_base + mt * 16 + er;
            int col = bn + n_base + nt * 8 + ec;
            #pragma unroll
            for (int half = 0; half < 2; half++) {
                int r2 = row + half * 8;
                float2 v;
                v.x = acc[mt][nt][half * 2 + 0];
                v.y = acc[mt][nt][half * 2 + 1];
                if (Res) {
                    float2 rr = *(const float2*)(Res + (size_t)r2 * N + col);
                    v.x += rr.x; v.y += rr.y;
                }
                if (GELU) { v.x = gelu_exact(v.x); v.y = gelu_exact(v.y); }
                *(float2*)(C + (size_t)r2 * N + col) = v;
            }
        }
    }
}

// ---------------- Flash attention (fp32, causal) ----------------
// Grid: (qtiles=32, B*H=32), 64 threads, one query row per thread.
__global__ void __launch_bounds__(64) attn_kernel(
    const float* __restrict__ Q, const float* __restrict__ K,
    const float* __restrict__ V, float* __restrict__ O)
{
    __shared__ float Qs[64][64];
    __shared__ float Ks[64][64];
    __shared__ float Vs[64][64];

    int qt = gridDim.x - 1 - blockIdx.x;   // heavy tiles first
    int bh = blockIdx.y;
    int b = bh / NHEADS, h = bh % NHEADS;
    int r = threadIdx.x;
    int sq = qt * 64 + r;

    const float* Qp = Q + (size_t)b * SEQ * DMODEL + h * HDIM;
    const float* Kp = K + (size_t)b * SEQ * DMODEL + h * HDIM;
    const float* Vp = V + (size_t)b * SEQ * DMODEL + h * HDIM;
    float*       Op = O + (size_t)b * SEQ * DMODEL + h * HDIM;

    #pragma unroll 8
    for (int t = 0; t < 64; t++)
        Qs[t][r] = Qp[(size_t)(qt * 64 + t) * DMODEL + r] * 0.125f;
    __syncthreads();

    float q[64];
    #pragma unroll
    for (int d = 0; d < 64; d++) q[d] = Qs[r][d];

    float o[64];
    #pragma unroll
    for (int d = 0; d < 64; d++) o[d] = 0.f;
    float mrun = -INFINITY, lrun = 0.f;

    for (int kt = 0; kt <= qt; kt++) {
        __syncthreads();
        #pragma unroll 8
        for (int t = 0; t < 64; t++) {
            size_t idx = (size_t)(kt * 64 + t) * DMODEL + r;
            Ks[t][r] = Kp[idx];
            Vs[t][r] = Vp[idx];
        }
        __syncthreads();

        bool diag = (kt == qt);
        for (int h2 = 0; h2 < 2; h2++) {
            float s[32];
            #pragma unroll
            for (int kk = 0; kk < 32; kk++) {
                float acc = 0.f;
                #pragma unroll
                for (int d4 = 0; d4 < 16; d4++) {
                    float4 kv = *(const float4*)&Ks[h2 * 32 + kk][d4 * 4];
                    acc += q[d4 * 4 + 0] * kv.x;
                    acc += q[d4 * 4 + 1] * kv.y;
                    acc += q[d4 * 4 + 2] * kv.z;
                    acc += q[d4 * 4 + 3] * kv.w;
                }
                s[kk] = acc;
            }
            if (diag) {
                #pragma unroll
                for (int kk = 0; kk < 32; kk++)
                    if (h2 * 32 + kk > r) s[kk] = -INFINITY;
            }
            float mt = mrun;
            #pragma unroll
            for (int kk = 0; kk < 32; kk++) mt = fmaxf(mt, s[kk]);
            float corr = __expf(mrun - mt);
            lrun *= corr;
            #pragma unroll
            for (int d = 0; d < 64; d++) o[d] *= corr;
            #pragma unroll
            for (int kk = 0; kk < 32; kk++) {
                float p = __expf(s[kk] - mt);
                lrun += p;
                s[kk] = p;
            }
            #pragma unroll
            for (int kk = 0; kk < 32; kk++) {
                float p = s[kk];
                #pragma unroll
                for (int d4 = 0; d4 < 16; d4++) {
                    float4 vv = *(const float4*)&Vs[h2 * 32 + kk][d4 * 4];
                    o[d4 * 4 + 0] += p * vv.x;
                    o[d4 * 4 + 1] += p * vv.y;
                    o[d4 * 4 + 2] += p * vv.z;
                    o[d4 * 4 + 3] += p * vv.w;
                }
            }
            mrun = mt;
        }
    }

    float inv = 1.f / lrun;
    float* outp = Op + (size_t)sq * DMODEL;
    #pragma unroll
    for (int d4 = 0; d4 < 16; d4++) {
        float4 v;
        v.x = o[d4 * 4 + 0] * inv; v.y = o[d4 * 4 + 1] * inv;
        v.z = o[d4 * 4 + 2] * inv; v.w = o[d4 * 4 + 3] * inv;
        *(float4*)(outp + d4 * 4) = v;
    }
}

// ---------------- launch ----------------
extern "C" void kernel_launch(void* const* d_in, const int* in_sizes, int n_in,
                              void* d_out, int out_size)
{
    const float* x     = (const float*)d_in[0];
    const float* Wq    = (const float*)d_in[1];
    const float* Wk    = (const float*)d_in[2];
    const float* Wv    = (const float*)d_in[3];
    const float* Wo    = (const float*)d_in[4];
    const float* Wup   = (const float*)d_in[5];
    const float* Wdown = (const float*)d_in[6];
    const float* ln1m  = (const float*)d_in[7];
    const float* ln1s  = (const float*)d_in[8];
    const float* ln2m  = (const float*)d_in[9];
    const float* ln2s  = (const float*)d_in[10];
    float* out = (float*)d_out;

    float *ln, *q, *k, *v, *pre, *x1, *mid;
    cudaGetSymbolAddress((void**)&ln,  g_ln);
    cudaGetSymbolAddress((void**)&q,   g_q);
    cudaGetSymbolAddress((void**)&k,   g_k);
    cudaGetSymbolAddress((void**)&v,   g_v);
    cudaGetSymbolAddress((void**)&pre, g_pre);
    cudaGetSymbolAddress((void**)&x1,  g_x1);
    cudaGetSymbolAddress((void**)&mid, g_mid);

    // LN1
    ln_kernel<<<MTOK, 256>>>(x, ln1m, ln1s, ln);

    // Q, K, V projections
    dim3 gD(DMODEL / 128, MTOK / 128);
    gemm_tf32_kernel<0><<<gD, 256>>>(ln, Wq, nullptr, q, MTOK, DMODEL, DMODEL);
    gemm_tf32_kernel<0><<<gD, 256>>>(ln, Wk, nullptr, k, MTOK, DMODEL, DMODEL);
    gemm_tf32_kernel<0><<<gD, 256>>>(ln, Wv, nullptr, v, MTOK, DMODEL, DMODEL);

    // causal flash attention
    attn_kernel<<<dim3(SEQ / 64, BATCH * NHEADS), 64>>>(q, k, v, pre);

    // output projection + residual (x1 = x + attn_out)
    gemm_tf32_kernel<0><<<gD, 256>>>(pre, Wo, x, x1, MTOK, DMODEL, DMODEL);

    // LN2
    ln_kernel<<<MTOK, 256>>>(x1, ln2m, ln2s, ln);

    // MLP up + exact GELU
    dim3 gUp(DFF / 128, MTOK / 128);
    gemm_tf32_kernel<1><<<gUp, 256>>>(ln, Wup, nullptr, mid, MTOK, DFF, DMODEL);

    // MLP down + residual -> output
    gemm_tf32_kernel<0><<<gD, 256>>>(mid, Wdown, x1, out, MTOK, DMODEL, DFF);
}

// round 3
// speedup vs baseline: 2.7535x; 1.7026x over previous
#include <cuda_runtime.h>
#include <math.h>

#define DMODEL 1024
#define SEQ    2048
#define BATCH  2
#define NHEADS 16
#define HDIM   64
#define MTOK   (BATCH*SEQ)   // 4096
#define DFF    (4*DMODEL)    // 4096
#define LN_EPS 1e-9f

// ---------------- scratch (device globals: allocation-free) ----------------
__device__ float g_ln [MTOK*DMODEL];
__device__ float g_q  [MTOK*DMODEL];
__device__ float g_k  [MTOK*DMODEL];
__device__ float g_v  [MTOK*DMODEL];
__device__ float g_pre[MTOK*DMODEL];
__device__ float g_x1 [MTOK*DMODEL];
__device__ float g_mid[MTOK*DFF];

// ---------------- LayerNorm (ddof=1, eps inside sqrt) ----------------
__global__ void __launch_bounds__(256) ln_kernel(
    const float* __restrict__ x,
    const float* __restrict__ msc,
    const float* __restrict__ ssc,
    float* __restrict__ out)
{
    __shared__ float xs[DMODEL];
    __shared__ float rs[16];
    int row = blockIdx.x;
    const float* xr = x + (size_t)row * DMODEL;
    float s = 0.f, s2 = 0.f;
    #pragma unroll
    for (int i = threadIdx.x; i < DMODEL; i += 256) {
        float v = xr[i]; xs[i] = v; s += v; s2 += v * v;
    }
    #pragma unroll
    for (int o = 16; o > 0; o >>= 1) {
        s  += __shfl_down_sync(0xffffffffu, s,  o);
        s2 += __shfl_down_sync(0xffffffffu, s2, o);
    }
    int wid = threadIdx.x >> 5;
    if ((threadIdx.x & 31) == 0) { rs[wid] = s; rs[8 + wid] = s2; }
    __syncthreads();
    s = 0.f; s2 = 0.f;
    #pragma unroll
    for (int w = 0; w < 8; w++) { s += rs[w]; s2 += rs[8 + w]; }
    float mean = s * (1.f / DMODEL);
    float var  = (s2 - (float)DMODEL * mean * mean) * (1.f / (DMODEL - 1));
    float inv  = rsqrtf(var + LN_EPS);
    float* outr = out + (size_t)row * DMODEL;
    #pragma unroll
    for (int i = threadIdx.x; i < DMODEL; i += 256)
        outr[i] = (xs[i] - mean) * inv * ssc[i] + msc[i];
}

// ---------------- helpers ----------------
__device__ __forceinline__ float gelu_exact(float x) {
    return 0.5f * x * (1.f + erff(x * 0.70710678118654752f));
}
__device__ __forceinline__ unsigned f2tf32(float f) {
    unsigned u;
    asm("cvt.rna.tf32.f32 %0, %1;" : "=r"(u) : "f"(f));
    return u;
}
__device__ __forceinline__ void mma_tf32(float c[4],
    unsigned a0, unsigned a1, unsigned a2, unsigned a3,
    unsigned b0, unsigned b1)
{
    asm volatile(
        "mma.sync.aligned.m16n8k8.row.col.f32.tf32.tf32.f32 "
        "{%0,%1,%2,%3}, {%4,%5,%6,%7}, {%8,%9}, {%0,%1,%2,%3};\n"
        : "+f"(c[0]), "+f"(c[1]), "+f"(c[2]), "+f"(c[3])
        : "r"(a0), "r"(a1), "r"(a2), "r"(a3), "r"(b0), "r"(b1));
}

// ---------------- TF32 GEMM  C = A(MxK)*W(NxK)^T [+Res][+GELU], 2-stage ----
#define GBM 128
#define GBN 128
#define GBK 32
#define GBKP 36
#define GABUF (GBM*GBKP)
#define GEMM_SMEM (2*2*GABUF*4)

template<int GELU>
__global__ void __launch_bounds__(256, 2) gemm_tf32_kernel(
    const float* __restrict__ A, const float* __restrict__ W,
    const float* __restrict__ Res, float* __restrict__ C,
    int M, int N, int K)
{
    extern __shared__ unsigned gsm[];
    unsigned* As = gsm;               // [2][128*36]
    unsigned* Bs = gsm + 2 * GABUF;   // [2][128*36]

    int bm = blockIdx.y * GBM, bn = blockIdx.x * GBN;
    int tid = threadIdx.x, lane = tid & 31, wid = tid >> 5;
    int m_base = (wid & 1) * 64;
    int n_base = (wid >> 1) * 32;

    int lr = tid >> 1;               // 0..127
    int lk = (tid & 1) * 16;         // 0 or 16
    const float* Ag = A + (size_t)(bm + lr) * K + lk;
    const float* Wg = W + (size_t)(bn + lr) * K + lk;
    unsigned* AsW = As + lr * GBKP + lk;
    unsigned* BsW = Bs + lr * GBKP + lk;

    float acc[4][4][4];
    #pragma unroll
    for (int mt = 0; mt < 4; mt++)
        #pragma unroll
        for (int nt = 0; nt < 4; nt++)
            #pragma unroll
            for (int e = 0; e < 4; e++) acc[mt][nt][e] = 0.f;

    int fr = lane >> 2, fc = lane & 3;
    int ntiles = K / GBK;

    float4 ra[4], rb[4];
    #pragma unroll
    for (int i = 0; i < 4; i++) {
        ra[i] = *(const float4*)(Ag + i * 4);
        rb[i] = *(const float4*)(Wg + i * 4);
    }
    #pragma unroll
    for (int i = 0; i < 4; i++) {
        uint4 ua = make_uint4(f2tf32(ra[i].x), f2tf32(ra[i].y), f2tf32(ra[i].z), f2tf32(ra[i].w));
        *(uint4*)(AsW + i * 4) = ua;
        uint4 ub = make_uint4(f2tf32(rb[i].x), f2tf32(rb[i].y), f2tf32(rb[i].z), f2tf32(rb[i].w));
        *(uint4*)(BsW + i * 4) = ub;
    }
    __syncthreads();

    for (int kb = 0; kb < ntiles; kb++) {
        int cur = kb & 1;
        bool more = (kb + 1 < ntiles);
        if (more) {
            int koff = (kb + 1) * GBK;
            #pragma unroll
            for (int i = 0; i < 4; i++) {
                ra[i] = *(const float4*)(Ag + koff + i * 4);
                rb[i] = *(const float4*)(Wg + koff + i * 4);
            }
        }

        const unsigned* Ac = As + cur * GABUF;
        const unsigned* Bc = Bs + cur * GABUF;
        #pragma unroll
        for (int ks = 0; ks < 4; ks++) {
            int k0 = ks * 8;
            unsigned a[4][4];
            #pragma unroll
            for (int mt = 0; mt < 4; mt++) {
                const unsigned* p = Ac + (m_base + mt * 16 + fr) * GBKP + k0 + fc;
                a[mt][0] = p[0];
                a[mt][1] = p[8 * GBKP];
                a[mt][2] = p[4];
                a[mt][3] = p[8 * GBKP + 4];
            }
            #pragma unroll
            for (int nt = 0; nt < 4; nt++) {
                const unsigned* p = Bc + (n_base + nt * 8 + fr) * GBKP + k0 + fc;
                unsigned b0 = p[0], b1 = p[4];
                #pragma unroll
                for (int mt = 0; mt < 4; mt++)
                    mma_tf32(acc[mt][nt], a[mt][0], a[mt][1], a[mt][2], a[mt][3], b0, b1);
            }
        }

        if (more) {
            int nxt = cur ^ 1;
            unsigned* An = AsW + nxt * GABUF;
            unsigned* Bn = BsW + nxt * GABUF;
            #pragma unroll
            for (int i = 0; i < 4; i++) {
                uint4 ua = make_uint4(f2tf32(ra[i].x), f2tf32(ra[i].y), f2tf32(ra[i].z), f2tf32(ra[i].w));
                *(uint4*)(An + i * 4) = ua;
                uint4 ub = make_uint4(f2tf32(rb[i].x), f2tf32(rb[i].y), f2tf32(rb[i].z), f2tf32(rb[i].w));
                *(uint4*)(Bn + i * 4) = ub;
            }
        }
        __syncthreads();
    }

    int er = lane >> 2, ec = (lane & 3) * 2;
    #pragma unroll
    for (int mt = 0; mt < 4; mt++) {
        #pragma unroll
        for (int nt = 0; nt < 4; nt++) {
            int row = bm + m_base + mt * 16 + er;
            int col = bn + n_base + nt * 8 + ec;
            #pragma unroll
            for (int half = 0; half < 2; half++) {
                int r2 = row + half * 8;
                float2 v;
                v.x = acc[mt][nt][half * 2 + 0];
                v.y = acc[mt][nt][half * 2 + 1];
                if (Res) {
                    float2 rr = *(const float2*)(Res + (size_t)r2 * N + col);
                    v.x += rr.x; v.y += rr.y;
                }
                if (GELU) { v.x = gelu_exact(v.x); v.y = gelu_exact(v.y); }
                *(float2*)(C + (size_t)r2 * N + col) = v;
            }
        }
    }
}

// ---------------- Flash attention, TF32 tensor cores ----------------
// 128 threads (4 warps); each warp owns 16 query rows of a 64-row q-tile.
// smem: Qs (reused as Ps) | Ks | Vs(transposed [d][key]), stride 68.
#define ASTR 68
#define ATT_SMEM (3*64*ASTR*4)

__global__ void __launch_bounds__(128) attn_mma_kernel(
    const float* __restrict__ Q, const float* __restrict__ K,
    const float* __restrict__ V, float* __restrict__ O)
{
    extern __shared__ unsigned sm[];
    unsigned* Qs = sm;                 // 64*68 (Q, later P)
    unsigned* Ks = sm + 64 * ASTR;
    unsigned* Vs = sm + 2 * 64 * ASTR; // [d][key]

    int qt = gridDim.x - 1 - blockIdx.x;   // heavy tiles first
    int bh = blockIdx.y;
    int b = bh >> 4, h = bh & 15;
    int tid = threadIdx.x, lane = tid & 31, w = tid >> 5;
    int fr = lane >> 2, fc = lane & 3;

    const float* Qp = Q + (size_t)b * SEQ * DMODEL + h * HDIM;
    const float* Kp = K + (size_t)b * SEQ * DMODEL + h * HDIM;
    const float* Vp = V + (size_t)b * SEQ * DMODEL + h * HDIM;
    float*       Op = O + (size_t)b * SEQ * DMODEL + h * HDIM;

    // load Q tile (scaled by 1/sqrt(64), tf32)
    {
        int r = tid >> 1, c0 = (tid & 1) * 32;
        const float* qp = Qp + (size_t)(qt * 64 + r) * DMODEL + c0;
        unsigned* qs = Qs + r * ASTR + c0;
        #pragma unroll
        for (int i = 0; i < 8; i++) {
            float4 v = *(const float4*)(qp + i * 4);
            qs[i * 4 + 0] = f2tf32(v.x * 0.125f);
            qs[i * 4 + 1] = f2tf32(v.y * 0.125f);
            qs[i * 4 + 2] = f2tf32(v.z * 0.125f);
            qs[i * 4 + 3] = f2tf32(v.w * 0.125f);
        }
    }
    __syncthreads();

    // Q fragments -> registers (held for all k-tiles)
    unsigned qa[8][4];
    {
        const unsigned* p0 = Qs + (w * 16 + fr) * ASTR + fc;
        #pragma unroll
        for (int ks = 0; ks < 8; ks++) {
            const unsigned* p = p0 + ks * 8;
            qa[ks][0] = p[0];
            qa[ks][1] = p[8 * ASTR];
            qa[ks][2] = p[4];
            qa[ks][3] = p[8 * ASTR + 4];
        }
    }

    float o[8][4];
    #pragma unroll
    for (int nt = 0; nt < 8; nt++)
        #pragma unroll
        for (int e = 0; e < 4; e++) o[nt][e] = 0.f;
    float mrun0 = -INFINITY, mrun1 = -INFINITY, l0 = 0.f, l1 = 0.f;

    unsigned* Ps = Qs;
    unsigned* prow = Ps + (w * 16 + fr) * ASTR;

    for (int kt = 0; kt <= qt; kt++) {
        __syncthreads();   // prev tile's smem reads done (also covers Qs->Ps handoff)
        // K tile: [key][d]
        {
            int r = tid >> 1, c0 = (tid & 1) * 32;
            const float* kp = Kp + (size_t)(kt * 64 + r) * DMODEL + c0;
            unsigned* ksm = Ks + r * ASTR + c0;
            #pragma unroll
            for (int i = 0; i < 8; i++) {
                float4 v = *(const float4*)(kp + i * 4);
                ksm[i * 4 + 0] = f2tf32(v.x);
                ksm[i * 4 + 1] = f2tf32(v.y);
                ksm[i * 4 + 2] = f2tf32(v.z);
                ksm[i * 4 + 3] = f2tf32(v.w);
            }
        }
        // V tile transposed: Vs[d][key]
        {
            int key = tid & 63;
            int dh = (tid >> 6) * 32;
            const float* vp = Vp + (size_t)(kt * 64 + key) * DMODEL;
            #pragma unroll
            for (int i = 0; i < 8; i++) {
                int d0 = dh + i * 4;
                float4 v = *(const float4*)(vp + d0);
                Vs[(d0 + 0) * ASTR + key] = f2tf32(v.x);
                Vs[(d0 + 1) * ASTR + key] = f2tf32(v.y);
                Vs[(d0 + 2) * ASTR + key] = f2tf32(v.z);
                Vs[(d0 + 3) * ASTR + key] = f2tf32(v.w);
            }
        }
        __syncthreads();

        // S = Q @ K^T  (16 q-rows x 64 keys per warp)
        float sc[8][4];
        #pragma unroll
        for (int nt = 0; nt < 8; nt++)
            #pragma unroll
            for (int e = 0; e < 4; e++) sc[nt][e] = 0.f;
        #pragma unroll
        for (int ks = 0; ks < 8; ks++) {
            #pragma unroll
            for (int nt = 0; nt < 8; nt++) {
                const unsigned* p = Ks + (nt * 8 + fr) * ASTR + ks * 8 + fc;
                mma_tf32(sc[nt], qa[ks][0], qa[ks][1], qa[ks][2], qa[ks][3], p[0], p[4]);
            }
        }

        // causal mask on diagonal tile
        if (kt == qt) {
            int r0 = w * 16 + fr, r1 = r0 + 8;
            #pragma unroll
            for (int nt = 0; nt < 8; nt++) {
                int c0 = nt * 8 + 2 * fc;
                if (c0     > r0) sc[nt][0] = -INFINITY;
                if (c0 + 1 > r0) sc[nt][1] = -INFINITY;
                if (c0     > r1) sc[nt][2] = -INFINITY;
                if (c0 + 1 > r1) sc[nt][3] = -INFINITY;
            }
        }

        // online softmax
        float m0 = -INFINITY, m1 = -INFINITY;
        #pragma unroll
        for (int nt = 0; nt < 8; nt++) {
            m0 = fmaxf(m0, fmaxf(sc[nt][0], sc[nt][1]));
            m1 = fmaxf(m1, fmaxf(sc[nt][2], sc[nt][3]));
        }
        m0 = fmaxf(m0, __shfl_xor_sync(0xffffffffu, m0, 1));
        m0 = fmaxf(m0, __shfl_xor_sync(0xffffffffu, m0, 2));
        m1 = fmaxf(m1, __shfl_xor_sync(0xffffffffu, m1, 1));
        m1 = fmaxf(m1, __shfl_xor_sync(0xffffffffu, m1, 2));
        float mn0 = fmaxf(mrun0, m0), mn1 = fmaxf(mrun1, m1);
        float corr0 = __expf(mrun0 - mn0), corr1 = __expf(mrun1 - mn1);
        l0 *= corr0; l1 *= corr1;
        #pragma unroll
        for (int nt = 0; nt < 8; nt++) {
            o[nt][0] *= corr0; o[nt][1] *= corr0;
            o[nt][2] *= corr1; o[nt][3] *= corr1;
        }
        #pragma unroll
        for (int nt = 0; nt < 8; nt++) {
            float p0 = __expf(sc[nt][0] - mn0);
            float p1 = __expf(sc[nt][1] - mn0);
            float p2 = __expf(sc[nt][2] - mn1);
            float p3 = __expf(sc[nt][3] - mn1);
            l0 += p0 + p1; l1 += p2 + p3;
            unsigned* pp = prow + nt * 8 + 2 * fc;
            pp[0] = f2tf32(p0); pp[1] = f2tf32(p1);
            pp[8 * ASTR] = f2tf32(p2); pp[8 * ASTR + 1] = f2tf32(p3);
        }
        mrun0 = mn0; mrun1 = mn1;
        __syncwarp();

        // O += P @ V   (P warp-local in smem; V^T fragments)
        #pragma unroll
        for (int ks = 0; ks < 8; ks++) {
            const unsigned* pa = prow + ks * 8 + fc;
            unsigned a0 = pa[0], a1 = pa[8 * ASTR], a2 = pa[4], a3 = pa[8 * ASTR + 4];
            #pragma unroll
            for (int nt = 0; nt < 8; nt++) {
                const unsigned* p = Vs + (nt * 8 + fr) * ASTR + ks * 8 + fc;
                mma_tf32(o[nt], a0, a1, a2, a3, p[0], p[4]);
            }
        }
        __syncwarp();   // PV reads done before next tile's P store
    }

    l0 += __shfl_xor_sync(0xffffffffu, l0, 1);
    l0 += __shfl_xor_sync(0xffffffffu, l0, 2);
    l1 += __shfl_xor_sync(0xffffffffu, l1, 1);
    l1 += __shfl_xor_sync(0xffffffffu, l1, 2);
    float inv0 = 1.f / l0, inv1 = 1.f / l1;

    int r0 = qt * 64 + w * 16 + fr;
    float* op0 = Op + (size_t)r0 * DMODEL;
    float* op1 = op0 + 8 * DMODEL;
    #pragma unroll
    for (int nt = 0; nt < 8; nt++) {
        int c = nt * 8 + 2 * fc;
        float2 v0; v0.x = o[nt][0] * inv0; v0.y = o[nt][1] * inv0;
        float2 v1; v1.x = o[nt][2] * inv1; v1.y = o[nt][3] * inv1;
        *(float2*)(op0 + c) = v0;
        *(float2*)(op1 + c) = v1;
    }
}

// ---------------- launch ----------------
extern "C" void kernel_launch(void* const* d_in, const int* in_sizes, int n_in,
                              void* d_out, int out_size)
{
    const float* x     = (const float*)d_in[0];
    const float* Wq    = (const float*)d_in[1];
    const float* Wk    = (const float*)d_in[2];
    const float* Wv    = (const float*)d_in[3];
    const float* Wo    = (const float*)d_in[4];
    const float* Wup   = (const float*)d_in[5];
    const float* Wdown = (const float*)d_in[6];
    const float* ln1m  = (const float*)d_in[7];
    const float* ln1s  = (const float*)d_in[8];
    const float* ln2m  = (const float*)d_in[9];
    const float* ln2s  = (const float*)d_in[10];
    float* out = (float*)d_out;

    float *ln, *q, *k, *v, *pre, *x1, *mid;
    cudaGetSymbolAddress((void**)&ln,  g_ln);
    cudaGetSymbolAddress((void**)&q,   g_q);
    cudaGetSymbolAddress((void**)&k,   g_k);
    cudaGetSymbolAddress((void**)&v,   g_v);
    cudaGetSymbolAddress((void**)&pre, g_pre);
    cudaGetSymbolAddress((void**)&x1,  g_x1);
    cudaGetSymbolAddress((void**)&mid, g_mid);

    cudaFuncSetAttribute(gemm_tf32_kernel<0>, cudaFuncAttributeMaxDynamicSharedMemorySize, GEMM_SMEM);
    cudaFuncSetAttribute(gemm_tf32_kernel<1>, cudaFuncAttributeMaxDynamicSharedMemorySize, GEMM_SMEM);
    cudaFuncSetAttribute(attn_mma_kernel,     cudaFuncAttributeMaxDynamicSharedMemorySize, ATT_SMEM);

    // LN1
    ln_kernel<<<MTOK, 256>>>(x, ln1m, ln1s, ln);

    // Q, K, V projections
    dim3 gD(DMODEL / 128, MTOK / 128);
    gemm_tf32_kernel<0><<<gD, 256, GEMM_SMEM>>>(ln, Wq, nullptr, q, MTOK, DMODEL, DMODEL);
    gemm_tf32_kernel<0><<<gD, 256, GEMM_SMEM>>>(ln, Wk, nullptr, k, MTOK, DMODEL, DMODEL);
    gemm_tf32_kernel<0><<<gD, 256, GEMM_SMEM>>>(ln, Wv, nullptr, v, MTOK, DMODEL, DMODEL);

    // causal flash attention (tensor cores)
    attn_mma_kernel<<<dim3(SEQ / 64, BATCH * NHEADS), 128, ATT_SMEM>>>(q, k, v, pre);

    // output projection + residual (x1 = x + attn_out)
    gemm_tf32_kernel<0><<<gD, 256, GEMM_SMEM>>>(pre, Wo, x, x1, MTOK, DMODEL, DMODEL);

    // LN2
    ln_kernel<<<MTOK, 256>>>(x1, ln2m, ln2s, ln);

    // MLP up + exact GELU
    dim3 gUp(DFF / 128, MTOK / 128);
    gemm_tf32_kernel<1><<<gUp, 256, GEMM_SMEM>>>(ln, Wup, nullptr, mid, MTOK, DFF, DMODEL);

    // MLP down + residual -> output
    gemm_tf32_kernel<0><<<gD, 256, GEMM_SMEM>>>(mid, Wdown, x1, out, MTOK, DMODEL, DFF);
}

// round 4
// speedup vs baseline: 3.0976x; 1.1249x over previous
#include <cuda_runtime.h>
#include <math.h>

#define DMODEL 1024
#define SEQ    2048
#define BATCH  2
#define NHEADS 16
#define HDIM   64
#define MTOK   (BATCH*SEQ)   // 4096
#define DFF    (4*DMODEL)    // 4096
#define LN_EPS 1e-9f

// ---------------- scratch (device globals: allocation-free) ----------------
__device__ float g_ln [MTOK*DMODEL];
__device__ float g_q  [MTOK*DMODEL];
__device__ float g_k  [MTOK*DMODEL];
__device__ float g_v  [MTOK*DMODEL];
__device__ float g_pre[MTOK*DMODEL];
__device__ float g_x1 [MTOK*DMODEL];
__device__ float g_mid[MTOK*DFF];

// ---------------- LayerNorm (ddof=1, eps inside sqrt) ----------------
__global__ void __launch_bounds__(256) ln_kernel(
    const float* __restrict__ x,
    const float* __restrict__ msc,
    const float* __restrict__ ssc,
    float* __restrict__ out)
{
    __shared__ float xs[DMODEL];
    __shared__ float rs[16];
    int row = blockIdx.x;
    const float* xr = x + (size_t)row * DMODEL;
    float s = 0.f, s2 = 0.f;
    #pragma unroll
    for (int i = threadIdx.x; i < DMODEL; i += 256) {
        float v = xr[i]; xs[i] = v; s += v; s2 += v * v;
    }
    #pragma unroll
    for (int o = 16; o > 0; o >>= 1) {
        s  += __shfl_down_sync(0xffffffffu, s,  o);
        s2 += __shfl_down_sync(0xffffffffu, s2, o);
    }
    int wid = threadIdx.x >> 5;
    if ((threadIdx.x & 31) == 0) { rs[wid] = s; rs[8 + wid] = s2; }
    __syncthreads();
    s = 0.f; s2 = 0.f;
    #pragma unroll
    for (int w = 0; w < 8; w++) { s += rs[w]; s2 += rs[8 + w]; }
    float mean = s * (1.f / DMODEL);
    float var  = (s2 - (float)DMODEL * mean * mean) * (1.f / (DMODEL - 1));
    float inv  = rsqrtf(var + LN_EPS);
    float* outr = out + (size_t)row * DMODEL;
    #pragma unroll
    for (int i = threadIdx.x; i < DMODEL; i += 256)
        outr[i] = (xs[i] - mean) * inv * ssc[i] + msc[i];
}

// ---------------- helpers ----------------
__device__ __forceinline__ float gelu_exact(float x) {
    return 0.5f * x * (1.f + erff(x * 0.70710678118654752f));
}
__device__ __forceinline__ unsigned f2tf32(float f) {
    unsigned u;
    asm("cvt.rna.tf32.f32 %0, %1;" : "=r"(u) : "f"(f));
    return u;
}
__device__ __forceinline__ void mma_tf32(float c[4],
    unsigned a0, unsigned a1, unsigned a2, unsigned a3,
    unsigned b0, unsigned b1)
{
    asm volatile(
        "mma.sync.aligned.m16n8k8.row.col.f32.tf32.tf32.f32 "
        "{%0,%1,%2,%3}, {%4,%5,%6,%7}, {%8,%9}, {%0,%1,%2,%3};\n"
        : "+f"(c[0]), "+f"(c[1]), "+f"(c[2]), "+f"(c[3])
        : "r"(a0), "r"(a1), "r"(a2), "r"(a3), "r"(b0), "r"(b1));
}
__device__ __forceinline__ void ldsm4(unsigned &r0, unsigned &r1,
                                      unsigned &r2, unsigned &r3, unsigned addr)
{
    asm volatile("ldmatrix.sync.aligned.m8n8.x4.shared.b16 {%0,%1,%2,%3}, [%4];"
        : "=r"(r0), "=r"(r1), "=r"(r2), "=r"(r3) : "r"(addr));
}
__device__ __forceinline__ unsigned smem_u32(const void* p) {
    return (unsigned)__cvta_generic_to_shared(p);
}

// ---------------- TF32 GEMM  C = A(MxK)*W(NxK)^T [+Res][+GELU], 2-stage ----
// A-fragment ldmatrix rows: m_base + (lane&15), k + 4*(lane>>4)
// B-fragment ldmatrix rows: n_base + (lane&7) + 8*((lane>>4)&1), k + 4*((lane>>3)&1)
//   -> regs (r0,r1) = b0,b1 of nt even; (r2,r3) = b0,b1 of nt odd.
#define GBM 128
#define GBN 128
#define GBK 32
#define GBKP 36
#define GABUF (GBM*GBKP)
#define GEMM_SMEM (2*2*GABUF*4)

template<int GELU>
__global__ void __launch_bounds__(256, 2) gemm_tf32_kernel(
    const float* __restrict__ A, const float* __restrict__ W,
    const float* __restrict__ Res, float* __restrict__ C,
    int M, int N, int K)
{
    extern __shared__ unsigned gsm[];
    unsigned* As = gsm;               // [2][128*36]
    unsigned* Bs = gsm + 2 * GABUF;   // [2][128*36]

    int bm = blockIdx.y * GBM, bn = blockIdx.x * GBN;
    int tid = threadIdx.x, lane = tid & 31, wid = tid >> 5;
    int m_base = (wid & 1) * 64;
    int n_base = (wid >> 1) * 32;

    int lr = tid >> 1;               // 0..127
    int lk = (tid & 1) * 16;         // 0 or 16
    const float* Ag = A + (size_t)(bm + lr) * K + lk;
    const float* Wg = W + (size_t)(bn + lr) * K + lk;
    unsigned* AsW = As + lr * GBKP + lk;
    unsigned* BsW = Bs + lr * GBKP + lk;

    // ldmatrix per-thread byte addresses
    unsigned aAddr0 = smem_u32(As) +
        (((m_base + (lane & 15)) * GBKP + ((lane >> 4) << 2)) << 2);
    unsigned bAddr0 = smem_u32(Bs) +
        (((n_base + (lane & 7) + (((lane >> 4) & 1) << 3)) * GBKP + (((lane >> 3) & 1) << 2)) << 2);

    float acc[4][4][4];
    #pragma unroll
    for (int mt = 0; mt < 4; mt++)
        #pragma unroll
        for (int nt = 0; nt < 4; nt++)
            #pragma unroll
            for (int e = 0; e < 4; e++) acc[mt][nt][e] = 0.f;

    int ntiles = K / GBK;

    float4 ra[4], rb[4];
    #pragma unroll
    for (int i = 0; i < 4; i++) {
        ra[i] = *(const float4*)(Ag + i * 4);
        rb[i] = *(const float4*)(Wg + i * 4);
    }
    #pragma unroll
    for (int i = 0; i < 4; i++) {
        uint4 ua = make_uint4(f2tf32(ra[i].x), f2tf32(ra[i].y), f2tf32(ra[i].z), f2tf32(ra[i].w));
        *(uint4*)(AsW + i * 4) = ua;
        uint4 ub = make_uint4(f2tf32(rb[i].x), f2tf32(rb[i].y), f2tf32(rb[i].z), f2tf32(rb[i].w));
        *(uint4*)(BsW + i * 4) = ub;
    }
    __syncthreads();

    for (int kb = 0; kb < ntiles; kb++) {
        int cur = kb & 1;
        bool more = (kb + 1 < ntiles);
        if (more) {
            int koff = (kb + 1) * GBK;
            #pragma unroll
            for (int i = 0; i < 4; i++) {
                ra[i] = *(const float4*)(Ag + koff + i * 4);
                rb[i] = *(const float4*)(Wg + koff + i * 4);
            }
        }

        unsigned aC = aAddr0 + cur * (GABUF * 4);
        unsigned bC = bAddr0 + cur * (GABUF * 4);
        #pragma unroll
        for (int ks = 0; ks < 4; ks++) {
            unsigned a[4][4];
            #pragma unroll
            for (int mt = 0; mt < 4; mt++)
                ldsm4(a[mt][0], a[mt][1], a[mt][2], a[mt][3],
                      aC + ((mt * 16 * GBKP + ks * 8) << 2));
            #pragma unroll
            for (int ntp = 0; ntp < 2; ntp++) {
                unsigned b0, b1, b2, b3;
                ldsm4(b0, b1, b2, b3, bC + ((ntp * 16 * GBKP + ks * 8) << 2));
                #pragma unroll
                for (int mt = 0; mt < 4; mt++) {
                    mma_tf32(acc[mt][2 * ntp + 0], a[mt][0], a[mt][1], a[mt][2], a[mt][3], b0, b1);
                    mma_tf32(acc[mt][2 * ntp + 1], a[mt][0], a[mt][1], a[mt][2], a[mt][3], b2, b3);
                }
            }
        }

        if (more) {
            int nxt = cur ^ 1;
            unsigned* An = AsW + nxt * GABUF;
            unsigned* Bn = BsW + nxt * GABUF;
            #pragma unroll
            for (int i = 0; i < 4; i++) {
                uint4 ua = make_uint4(f2tf32(ra[i].x), f2tf32(ra[i].y), f2tf32(ra[i].z), f2tf32(ra[i].w));
                *(uint4*)(An + i * 4) = ua;
                uint4 ub = make_uint4(f2tf32(rb[i].x), f2tf32(rb[i].y), f2tf32(rb[i].z), f2tf32(rb[i].w));
                *(uint4*)(Bn + i * 4) = ub;
            }
        }
        __syncthreads();
    }

    int er = lane >> 2, ec = (lane & 3) * 2;
    #pragma unroll
    for (int mt = 0; mt < 4; mt++) {
        #pragma unroll
        for (int nt = 0; nt < 4; nt++) {
            int row = bm + m_base + mt * 16 + er;
            int col = bn + n_base + nt * 8 + ec;
            #pragma unroll
            for (int half = 0; half < 2; half++) {
                int r2 = row + half * 8;
                float2 v;
                v.x = acc[mt][nt][half * 2 + 0];
                v.y = acc[mt][nt][half * 2 + 1];
                if (Res) {
                    float2 rr = *(const float2*)(Res + (size_t)r2 * N + col);
                    v.x += rr.x; v.y += rr.y;
                }
                if (GELU) { v.x = gelu_exact(v.x); v.y = gelu_exact(v.y); }
                *(float2*)(C + (size_t)r2 * N + col) = v;
            }
        }
    }
}

// ---------------- Flash attention, TF32 tensor cores + ldmatrix ----------------
#define ASTR 68
#define ATT_SMEM (3*64*ASTR*4)

__global__ void __launch_bounds__(128) attn_mma_kernel(
    const float* __restrict__ Q, const float* __restrict__ K,
    const float* __restrict__ V, float* __restrict__ O)
{
    extern __shared__ unsigned sm[];
    unsigned* Qs = sm;                 // 64*68 (Q, later P)
    unsigned* Ks = sm + 64 * ASTR;
    unsigned* Vs = sm + 2 * 64 * ASTR; // [d][key]

    int qt = gridDim.x - 1 - blockIdx.x;   // heavy tiles first
    int bh = blockIdx.y;
    int b = bh >> 4, h = bh & 15;
    int tid = threadIdx.x, lane = tid & 31, w = tid >> 5;
    int fr = lane >> 2, fc = lane & 3;

    const float* Qp = Q + (size_t)b * SEQ * DMODEL + h * HDIM;
    const float* Kp = K + (size_t)b * SEQ * DMODEL + h * HDIM;
    const float* Vp = V + (size_t)b * SEQ * DMODEL + h * HDIM;
    float*       Op = O + (size_t)b * SEQ * DMODEL + h * HDIM;

    // ldmatrix addresses
    unsigned aSel = ((lane & 15) * ASTR + ((lane >> 4) << 2)) << 2;  // A-pattern
    unsigned bSel = (((lane & 7) + (((lane >> 4) & 1) << 3)) * ASTR
                     + (((lane >> 3) & 1) << 2)) << 2;               // B-pattern
    unsigned qAddr = smem_u32(Qs) + ((w * 16 * ASTR) << 2) + aSel;   // Q / P frags
    unsigned kAddr = smem_u32(Ks) + bSel;
    unsigned vAddr = smem_u32(Vs) + bSel;

    // load Q tile (scaled by 1/sqrt(64), tf32)
    {
        int r = tid >> 1, c0 = (tid & 1) * 32;
        const float* qp = Qp + (size_t)(qt * 64 + r) * DMODEL + c0;
        unsigned* qs = Qs + r * ASTR + c0;
        #pragma unroll
        for (int i = 0; i < 8; i++) {
            float4 v = *(const float4*)(qp + i * 4);
            qs[i * 4 + 0] = f2tf32(v.x * 0.125f);
            qs[i * 4 + 1] = f2tf32(v.y * 0.125f);
            qs[i * 4 + 2] = f2tf32(v.z * 0.125f);
            qs[i * 4 + 3] = f2tf32(v.w * 0.125f);
        }
    }
    __syncthreads();

    unsigned qa[8][4];
    #pragma unroll
    for (int ks = 0; ks < 8; ks++)
        ldsm4(qa[ks][0], qa[ks][1], qa[ks][2], qa[ks][3], qAddr + ((ks * 8) << 2));

    float o[8][4];
    #pragma unroll
    for (int nt = 0; nt < 8; nt++)
        #pragma unroll
        for (int e = 0; e < 4; e++) o[nt][e] = 0.f;
    float mrun0 = -INFINITY, mrun1 = -INFINITY, l0 = 0.f, l1 = 0.f;

    unsigned* prow = Qs + (w * 16 + fr) * ASTR;

    for (int kt = 0; kt <= qt; kt++) {
        __syncthreads();
        // K tile: [key][d]
        {
            int r = tid >> 1, c0 = (tid & 1) * 32;
            const float* kp = Kp + (size_t)(kt * 64 + r) * DMODEL + c0;
            unsigned* ksm = Ks + r * ASTR + c0;
            #pragma unroll
            for (int i = 0; i < 8; i++) {
                float4 v = *(const float4*)(kp + i * 4);
                ksm[i * 4 + 0] = f2tf32(v.x);
                ksm[i * 4 + 1] = f2tf32(v.y);
                ksm[i * 4 + 2] = f2tf32(v.z);
                ksm[i * 4 + 3] = f2tf32(v.w);
            }
        }
        // V tile transposed: Vs[d][key]
        {
            int key = tid & 63;
            int dh = (tid >> 6) * 32;
            const float* vp = Vp + (size_t)(kt * 64 + key) * DMODEL;
            #pragma unroll
            for (int i = 0; i < 8; i++) {
                int d0 = dh + i * 4;
                float4 v = *(const float4*)(vp + d0);
                Vs[(d0 + 0) * ASTR + key] = f2tf32(v.x);
                Vs[(d0 + 1) * ASTR + key] = f2tf32(v.y);
                Vs[(d0 + 2) * ASTR + key] = f2tf32(v.z);
                Vs[(d0 + 3) * ASTR + key] = f2tf32(v.w);
            }
        }
        __syncthreads();

        // S = Q @ K^T
        float sc[8][4];
        #pragma unroll
        for (int nt = 0; nt < 8; nt++)
            #pragma unroll
            for (int e = 0; e < 4; e++) sc[nt][e] = 0.f;
        #pragma unroll
        for (int ks = 0; ks < 8; ks++) {
            #pragma unroll
            for (int ntp = 0; ntp < 4; ntp++) {
                unsigned b0, b1, b2, b3;
                ldsm4(b0, b1, b2, b3, kAddr + ((ntp * 16 * ASTR + ks * 8) << 2));
                mma_tf32(sc[2 * ntp + 0], qa[ks][0], qa[ks][1], qa[ks][2], qa[ks][3], b0, b1);
                mma_tf32(sc[2 * ntp + 1], qa[ks][0], qa[ks][1], qa[ks][2], qa[ks][3], b2, b3);
            }
        }

        // causal mask on diagonal tile
        if (kt == qt) {
            int r0 = w * 16 + fr, r1 = r0 + 8;
            #pragma unroll
            for (int nt = 0; nt < 8; nt++) {
                int c0 = nt * 8 + 2 * fc;
                if (c0     > r0) sc[nt][0] = -INFINITY;
                if (c0 + 1 > r0) sc[nt][1] = -INFINITY;
                if (c0     > r1) sc[nt][2] = -INFINITY;
                if (c0 + 1 > r1) sc[nt][3] = -INFINITY;
            }
        }

        // online softmax
        float m0 = -INFINITY, m1 = -INFINITY;
        #pragma unroll
        for (int nt = 0; nt < 8; nt++) {
            m0 = fmaxf(m0, fmaxf(sc[nt][0], sc[nt][1]));
            m1 = fmaxf(m1, fmaxf(sc[nt][2], sc[nt][3]));
        }
        m0 = fmaxf(m0, __shfl_xor_sync(0xffffffffu, m0, 1));
        m0 = fmaxf(m0, __shfl_xor_sync(0xffffffffu, m0, 2));
        m1 = fmaxf(m1, __shfl_xor_sync(0xffffffffu, m1, 1));
        m1 = fmaxf(m1, __shfl_xor_sync(0xffffffffu, m1, 2));
        float mn0 = fmaxf(mrun0, m0), mn1 = fmaxf(mrun1, m1);
        float corr0 = __expf(mrun0 - mn0), corr1 = __expf(mrun1 - mn1);
        l0 *= corr0; l1 *= corr1;
        #pragma unroll
        for (int nt = 0; nt < 8; nt++) {
            o[nt][0] *= corr0; o[nt][1] *= corr0;
            o[nt][2] *= corr1; o[nt][3] *= corr1;
        }
        #pragma unroll
        for (int nt = 0; nt < 8; nt++) {
            float p0 = __expf(sc[nt][0] - mn0);
            float p1 = __expf(sc[nt][1] - mn0);
            float p2 = __expf(sc[nt][2] - mn1);
            float p3 = __expf(sc[nt][3] - mn1);
            l0 += p0 + p1; l1 += p2 + p3;
            unsigned* pp = prow + nt * 8 + 2 * fc;
            *(uint2*)pp = make_uint2(f2tf32(p0), f2tf32(p1));
            *(uint2*)(pp + 8 * ASTR) = make_uint2(f2tf32(p2), f2tf32(p3));
        }
        mrun0 = mn0; mrun1 = mn1;
        __syncwarp();

        // O += P @ V
        #pragma unroll
        for (int ks = 0; ks < 8; ks++) {
            unsigned a0, a1, a2, a3;
            ldsm4(a0, a1, a2, a3, qAddr + ((ks * 8) << 2));
            #pragma unroll
            for (int ntp = 0; ntp < 4; ntp++) {
                unsigned b0, b1, b2, b3;
                ldsm4(b0, b1, b2, b3, vAddr + ((ntp * 16 * ASTR + ks * 8) << 2));
                mma_tf32(o[2 * ntp + 0], a0, a1, a2, a3, b0, b1);
                mma_tf32(o[2 * ntp + 1], a0, a1, a2, a3, b2, b3);
            }
        }
        __syncwarp();   // PV reads done before next tile overwrites P/K/V
    }

    l0 += __shfl_xor_sync(0xffffffffu, l0, 1);
    l0 += __shfl_xor_sync(0xffffffffu, l0, 2);
    l1 += __shfl_xor_sync(0xffffffffu, l1, 1);
    l1 += __shfl_xor_sync(0xffffffffu, l1, 2);
    float inv0 = 1.f / l0, inv1 = 1.f / l1;

    int r0 = qt * 64 + w * 16 + fr;
    float* op0 = Op + (size_t)r0 * DMODEL;
    float* op1 = op0 + 8 * DMODEL;
    #pragma unroll
    for (int nt = 0; nt < 8; nt++) {
        int c = nt * 8 + 2 * fc;
        float2 v0; v0.x = o[nt][0] * inv0; v0.y = o[nt][1] * inv0;
        float2 v1; v1.x = o[nt][2] * inv1; v1.y = o[nt][3] * inv1;
        *(float2*)(op0 + c) = v0;
        *(float2*)(op1 + c) = v1;
    }
}

// ---------------- launch ----------------
extern "C" void kernel_launch(void* const* d_in, const int* in_sizes, int n_in,
                              void* d_out, int out_size)
{
    const float* x     = (const float*)d_in[0];
    const float* Wq    = (const float*)d_in[1];
    const float* Wk    = (const float*)d_in[2];
    const float* Wv    = (const float*)d_in[3];
    const float* Wo    = (const float*)d_in[4];
    const float* Wup   = (const float*)d_in[5];
    const float* Wdown = (const float*)d_in[6];
    const float* ln1m  = (const float*)d_in[7];
    const float* ln1s  = (const float*)d_in[8];
    const float* ln2m  = (const float*)d_in[9];
    const float* ln2s  = (const float*)d_in[10];
    float* out = (float*)d_out;

    float *ln, *q, *k, *v, *pre, *x1, *mid;
    cudaGetSymbolAddress((void**)&ln,  g_ln);
    cudaGetSymbolAddress((void**)&q,   g_q);
    cudaGetSymbolAddress((void**)&k,   g_k);
    cudaGetSymbolAddress((void**)&v,   g_v);
    cudaGetSymbolAddress((void**)&pre, g_pre);
    cudaGetSymbolAddress((void**)&x1,  g_x1);
    cudaGetSymbolAddress((void**)&mid, g_mid);

    cudaFuncSetAttribute(gemm_tf32_kernel<0>, cudaFuncAttributeMaxDynamicSharedMemorySize, GEMM_SMEM);
    cudaFuncSetAttribute(gemm_tf32_kernel<1>, cudaFuncAttributeMaxDynamicSharedMemorySize, GEMM_SMEM);
    cudaFuncSetAttribute(attn_mma_kernel,     cudaFuncAttributeMaxDynamicSharedMemorySize, ATT_SMEM);

    // LN1
    ln_kernel<<<MTOK, 256>>>(x, ln1m, ln1s, ln);

    // Q, K, V projections
    dim3 gD(DMODEL / 128, MTOK / 128);
    gemm_tf32_kernel<0><<<gD, 256, GEMM_SMEM>>>(ln, Wq, nullptr, q, MTOK, DMODEL, DMODEL);
    gemm_tf32_kernel<0><<<gD, 256, GEMM_SMEM>>>(ln, Wk, nullptr, k, MTOK, DMODEL, DMODEL);
    gemm_tf32_kernel<0><<<gD, 256, GEMM_SMEM>>>(ln, Wv, nullptr, v, MTOK, DMODEL, DMODEL);

    // causal flash attention (tensor cores)
    attn_mma_kernel<<<dim3(SEQ / 64, BATCH * NHEADS), 128, ATT_SMEM>>>(q, k, v, pre);

    // output projection + residual (x1 = x + attn_out)
    gemm_tf32_kernel<0><<<gD, 256, GEMM_SMEM>>>(pre, Wo, x, x1, MTOK, DMODEL, DMODEL);

    // LN2
    ln_kernel<<<MTOK, 256>>>(x1, ln2m, ln2s, ln);

    // MLP up + exact GELU
    dim3 gUp(DFF / 128, MTOK / 128);
    gemm_tf32_kernel<1><<<gUp, 256, GEMM_SMEM>>>(ln, Wup, nullptr, mid, MTOK, DFF, DMODEL);

    // MLP down + residual -> output
    gemm_tf32_kernel<0><<<gD, 256, GEMM_SMEM>>>(mid, Wdown, x1, out, MTOK, DMODEL, DFF);
}

// round 5
// speedup vs baseline: 3.2323x; 1.0435x over previous
#include <cuda_runtime.h>
#include <math.h>

#define DMODEL 1024
#define SEQ    2048
#define BATCH  2
#define NHEADS 16
#define HDIM   64
#define MTOK   (BATCH*SEQ)   // 4096
#define DFF    (4*DMODEL)    // 4096
#define LN_EPS 1e-9f

// ---------------- scratch (device globals: allocation-free) ----------------
__device__ float g_ln [MTOK*DMODEL];
__device__ float g_q  [MTOK*DMODEL];
__device__ float g_k  [MTOK*DMODEL];
__device__ float g_v  [MTOK*DMODEL];
__device__ float g_pre[MTOK*DMODEL];
__device__ float g_x1 [MTOK*DMODEL];
__device__ float g_mid[MTOK*DFF];

// ---------------- LayerNorm (ddof=1, eps inside sqrt) ----------------
__global__ void __launch_bounds__(256) ln_kernel(
    const float* __restrict__ x,
    const float* __restrict__ msc,
    const float* __restrict__ ssc,
    float* __restrict__ out)
{
    __shared__ float xs[DMODEL];
    __shared__ float rs[16];
    int row = blockIdx.x;
    const float* xr = x + (size_t)row * DMODEL;
    float s = 0.f, s2 = 0.f;
    #pragma unroll
    for (int i = threadIdx.x; i < DMODEL; i += 256) {
        float v = xr[i]; xs[i] = v; s += v; s2 += v * v;
    }
    #pragma unroll
    for (int o = 16; o > 0; o >>= 1) {
        s  += __shfl_down_sync(0xffffffffu, s,  o);
        s2 += __shfl_down_sync(0xffffffffu, s2, o);
    }
    int wid = threadIdx.x >> 5;
    if ((threadIdx.x & 31) == 0) { rs[wid] = s; rs[8 + wid] = s2; }
    __syncthreads();
    s = 0.f; s2 = 0.f;
    #pragma unroll
    for (int w = 0; w < 8; w++) { s += rs[w]; s2 += rs[8 + w]; }
    float mean = s * (1.f / DMODEL);
    float var  = (s2 - (float)DMODEL * mean * mean) * (1.f / (DMODEL - 1));
    float inv  = rsqrtf(var + LN_EPS);
    float* outr = out + (size_t)row * DMODEL;
    #pragma unroll
    for (int i = threadIdx.x; i < DMODEL; i += 256)
        outr[i] = (xs[i] - mean) * inv * ssc[i] + msc[i];
}

// ---------------- helpers ----------------
__device__ __forceinline__ float gelu_exact(float x) {
    return 0.5f * x * (1.f + erff(x * 0.70710678118654752f));
}
__device__ __forceinline__ void mma_tf32(float c[4],
    unsigned a0, unsigned a1, unsigned a2, unsigned a3,
    unsigned b0, unsigned b1)
{
    asm volatile(
        "mma.sync.aligned.m16n8k8.row.col.f32.tf32.tf32.f32 "
        "{%0,%1,%2,%3}, {%4,%5,%6,%7}, {%8,%9}, {%0,%1,%2,%3};\n"
        : "+f"(c[0]), "+f"(c[1]), "+f"(c[2]), "+f"(c[3])
        : "r"(a0), "r"(a1), "r"(a2), "r"(a3), "r"(b0), "r"(b1));
}
__device__ __forceinline__ void ldsm4(unsigned &r0, unsigned &r1,
                                      unsigned &r2, unsigned &r3, unsigned addr)
{
    asm volatile("ldmatrix.sync.aligned.m8n8.x4.shared.b16 {%0,%1,%2,%3}, [%4];"
        : "=r"(r0), "=r"(r1), "=r"(r2), "=r"(r3) : "r"(addr));
}
__device__ __forceinline__ unsigned smem_u32(const void* p) {
    return (unsigned)__cvta_generic_to_shared(p);
}
__device__ __forceinline__ void cpasync16(unsigned dst, const void* src) {
    asm volatile("cp.async.cg.shared.global [%0], [%1], 16;" :: "r"(dst), "l"(src));
}
#define CP_COMMIT asm volatile("cp.async.commit_group;")
#define CP_WAIT0  asm volatile("cp.async.wait_group 0;")

// ---------------- TF32 GEMM  C = A(MxK)*W(NxK)^T [+Res][+GELU], cp.async ----
// Raw fp32 bits in smem; mma.tf32 truncates to tf32 in hardware.
#define GBM 128
#define GBN 128
#define GBK 32
#define GBKP 36
#define GABUF (GBM*GBKP)
#define GEMM_SMEM (2*2*GABUF*4)

template<int GELU>
__global__ void __launch_bounds__(256, 2) gemm_tf32_kernel(
    const float* __restrict__ A, const float* __restrict__ W,
    const float* __restrict__ Res, float* __restrict__ C,
    int M, int N, int K)
{
    extern __shared__ unsigned gsm[];
    unsigned* As = gsm;               // [2][128*36]
    unsigned* Bs = gsm + 2 * GABUF;   // [2][128*36]

    int bm = blockIdx.y * GBM, bn = blockIdx.x * GBN;
    int tid = threadIdx.x, lane = tid & 31, wid = tid >> 5;
    int m_base = (wid & 1) * 64;
    int n_base = (wid >> 1) * 32;

    int lr = tid >> 1;               // 0..127
    int lk = (tid & 1) * 16;         // 0 or 16
    const float* Ag = A + (size_t)(bm + lr) * K + lk;
    const float* Wg = W + (size_t)(bn + lr) * K + lk;
    unsigned aDst = smem_u32(As) + ((lr * GBKP + lk) << 2);
    unsigned bDst = aDst + 2 * GABUF * 4;

    // ldmatrix per-thread byte addresses
    unsigned aAddr0 = smem_u32(As) +
        (((m_base + (lane & 15)) * GBKP + ((lane >> 4) << 2)) << 2);
    unsigned bAddr0 = smem_u32(Bs) +
        (((n_base + (lane & 7) + (((lane >> 4) & 1) << 3)) * GBKP + (((lane >> 3) & 1) << 2)) << 2);

    float acc[4][4][4];
    #pragma unroll
    for (int mt = 0; mt < 4; mt++)
        #pragma unroll
        for (int nt = 0; nt < 4; nt++)
            #pragma unroll
            for (int e = 0; e < 4; e++) acc[mt][nt][e] = 0.f;

    int ntiles = K / GBK;

    // prologue: stage tile 0 into buffer 0
    #pragma unroll
    for (int i = 0; i < 4; i++) {
        cpasync16(aDst + i * 16, Ag + i * 4);
        cpasync16(bDst + i * 16, Wg + i * 4);
    }
    CP_COMMIT;

    for (int kb = 0; kb < ntiles; kb++) {
        CP_WAIT0;          // tile kb landed (this thread)
        __syncthreads();   // visible block-wide; prev-buffer reads done

        if (kb + 1 < ntiles) {           // prefetch kb+1 into other buffer
            int st = (kb + 1) & 1;
            int koff = (kb + 1) * GBK;
            unsigned aD = aDst + st * (GABUF * 4);
            unsigned bD = bDst + st * (GABUF * 4);
            #pragma unroll
            for (int i = 0; i < 4; i++) {
                cpasync16(aD + i * 16, Ag + koff + i * 4);
                cpasync16(bD + i * 16, Wg + koff + i * 4);
            }
        }
        CP_COMMIT;

        unsigned aC = aAddr0 + (kb & 1) * (GABUF * 4);
        unsigned bC = bAddr0 + (kb & 1) * (GABUF * 4);
        #pragma unroll
        for (int ks = 0; ks < 4; ks++) {
            unsigned a[4][4];
            #pragma unroll
            for (int mt = 0; mt < 4; mt++)
                ldsm4(a[mt][0], a[mt][1], a[mt][2], a[mt][3],
                      aC + ((mt * 16 * GBKP + ks * 8) << 2));
            #pragma unroll
            for (int ntp = 0; ntp < 2; ntp++) {
                unsigned b0, b1, b2, b3;
                ldsm4(b0, b1, b2, b3, bC + ((ntp * 16 * GBKP + ks * 8) << 2));
                #pragma unroll
                for (int mt = 0; mt < 4; mt++) {
                    mma_tf32(acc[mt][2 * ntp + 0], a[mt][0], a[mt][1], a[mt][2], a[mt][3], b0, b1);
                    mma_tf32(acc[mt][2 * ntp + 1], a[mt][0], a[mt][1], a[mt][2], a[mt][3], b2, b3);
                }
            }
        }
    }

    int er = lane >> 2, ec = (lane & 3) * 2;
    #pragma unroll
    for (int mt = 0; mt < 4; mt++) {
        #pragma unroll
        for (int nt = 0; nt < 4; nt++) {
            int row = bm + m_base + mt * 16 + er;
            int col = bn + n_base + nt * 8 + ec;
            #pragma unroll
            for (int half = 0; half < 2; half++) {
                int r2 = row + half * 8;
                float2 v;
                v.x = acc[mt][nt][half * 2 + 0];
                v.y = acc[mt][nt][half * 2 + 1];
                if (Res) {
                    float2 rr = *(const float2*)(Res + (size_t)r2 * N + col);
                    v.x += rr.x; v.y += rr.y;
                }
                if (GELU) { v.x = gelu_exact(v.x); v.y = gelu_exact(v.y); }
                *(float2*)(C + (size_t)r2 * N + col) = v;
            }
        }
    }
}

// ---------------- Flash attention, TF32 tensor cores + ldmatrix + cp.async ----
#define ASTR 68
#define ATT_SMEM (3*64*ASTR*4)

__global__ void __launch_bounds__(128) attn_mma_kernel(
    const float* __restrict__ Q, const float* __restrict__ K,
    const float* __restrict__ V, float* __restrict__ O)
{
    extern __shared__ unsigned sm[];
    unsigned* Qs = sm;                 // 64*68 (Q, later P)
    unsigned* Ks = sm + 64 * ASTR;
    unsigned* Vs = sm + 2 * 64 * ASTR; // [d][key]

    int qt = gridDim.x - 1 - blockIdx.x;   // heavy tiles first
    int bh = blockIdx.y;
    int b = bh >> 4, h = bh & 15;
    int tid = threadIdx.x, lane = tid & 31, w = tid >> 5;
    int fr = lane >> 2, fc = lane & 3;

    const float* Qp = Q + (size_t)b * SEQ * DMODEL + h * HDIM;
    const float* Kp = K + (size_t)b * SEQ * DMODEL + h * HDIM;
    const float* Vp = V + (size_t)b * SEQ * DMODEL + h * HDIM;
    float*       Op = O + (size_t)b * SEQ * DMODEL + h * HDIM;

    // ldmatrix addresses
    unsigned aSel = ((lane & 15) * ASTR + ((lane >> 4) << 2)) << 2;  // A-pattern
    unsigned bSel = (((lane & 7) + (((lane >> 4) & 1) << 3)) * ASTR
                     + (((lane >> 3) & 1) << 2)) << 2;               // B-pattern
    unsigned qAddr = smem_u32(Qs) + ((w * 16 * ASTR) << 2) + aSel;   // Q / P frags
    unsigned kAddr = smem_u32(Ks) + bSel;
    unsigned vAddr = smem_u32(Vs) + bSel;

    int ldr = tid >> 1, ldc = (tid & 1) * 32;
    unsigned kDst = smem_u32(Ks) + ((ldr * ASTR + ldc) << 2);

    // load Q tile (scaled by 1/sqrt(64); raw fp32 bits, mma truncates)
    {
        const float* qp = Qp + (size_t)(qt * 64 + ldr) * DMODEL + ldc;
        unsigned* qs = Qs + ldr * ASTR + ldc;
        #pragma unroll
        for (int i = 0; i < 8; i++) {
            float4 v = *(const float4*)(qp + i * 4);
            qs[i * 4 + 0] = __float_as_uint(v.x * 0.125f);
            qs[i * 4 + 1] = __float_as_uint(v.y * 0.125f);
            qs[i * 4 + 2] = __float_as_uint(v.z * 0.125f);
            qs[i * 4 + 3] = __float_as_uint(v.w * 0.125f);
        }
    }
    __syncthreads();

    unsigned qa[8][4];
    #pragma unroll
    for (int ks = 0; ks < 8; ks++)
        ldsm4(qa[ks][0], qa[ks][1], qa[ks][2], qa[ks][3], qAddr + ((ks * 8) << 2));

    float o[8][4];
    #pragma unroll
    for (int nt = 0; nt < 8; nt++)
        #pragma unroll
        for (int e = 0; e < 4; e++) o[nt][e] = 0.f;
    float mrun0 = -INFINITY, mrun1 = -INFINITY, l0 = 0.f, l1 = 0.f;

    unsigned* prow = Qs + (w * 16 + fr) * ASTR;

    for (int kt = 0; kt <= qt; kt++) {
        __syncthreads();    // prev tile's smem reads done
        // K tile via cp.async (overlaps with V transpose below)
        {
            const float* kp = Kp + (size_t)(kt * 64 + ldr) * DMODEL + ldc;
            #pragma unroll
            for (int i = 0; i < 8; i++)
                cpasync16(kDst + i * 16, kp + i * 4);
            CP_COMMIT;
        }
        // V tile transposed: Vs[d][key] (raw bits)
        {
            int key = tid & 63;
            int dh = (tid >> 6) * 32;
            const float* vp = Vp + (size_t)(kt * 64 + key) * DMODEL;
            #pragma unroll
            for (int i = 0; i < 8; i++) {
                int d0 = dh + i * 4;
                float4 v = *(const float4*)(vp + d0);
                Vs[(d0 + 0) * ASTR + key] = __float_as_uint(v.x);
                Vs[(d0 + 1) * ASTR + key] = __float_as_uint(v.y);
                Vs[(d0 + 2) * ASTR + key] = __float_as_uint(v.z);
                Vs[(d0 + 3) * ASTR + key] = __float_as_uint(v.w);
            }
        }
        CP_WAIT0;
        __syncthreads();

        // S = Q @ K^T
        float sc[8][4];
        #pragma unroll
        for (int nt = 0; nt < 8; nt++)
            #pragma unroll
            for (int e = 0; e < 4; e++) sc[nt][e] = 0.f;
        #pragma unroll
        for (int ks = 0; ks < 8; ks++) {
            #pragma unroll
            for (int ntp = 0; ntp < 4; ntp++) {
                unsigned b0, b1, b2, b3;
                ldsm4(b0, b1, b2, b3, kAddr + ((ntp * 16 * ASTR + ks * 8) << 2));
                mma_tf32(sc[2 * ntp + 0], qa[ks][0], qa[ks][1], qa[ks][2], qa[ks][3], b0, b1);
                mma_tf32(sc[2 * ntp + 1], qa[ks][0], qa[ks][1], qa[ks][2], qa[ks][3], b2, b3);
            }
        }

        // causal mask on diagonal tile
        if (kt == qt) {
            int r0 = w * 16 + fr, r1 = r0 + 8;
            #pragma unroll
            for (int nt = 0; nt < 8; nt++) {
                int c0 = nt * 8 + 2 * fc;
                if (c0     > r0) sc[nt][0] = -INFINITY;
                if (c0 + 1 > r0) sc[nt][1] = -INFINITY;
                if (c0     > r1) sc[nt][2] = -INFINITY;
                if (c0 + 1 > r1) sc[nt][3] = -INFINITY;
            }
        }

        // online softmax
        float m0 = -INFINITY, m1 = -INFINITY;
        #pragma unroll
        for (int nt = 0; nt < 8; nt++) {
            m0 = fmaxf(m0, fmaxf(sc[nt][0], sc[nt][1]));
            m1 = fmaxf(m1, fmaxf(sc[nt][2], sc[nt][3]));
        }
        m0 = fmaxf(m0, __shfl_xor_sync(0xffffffffu, m0, 1));
        m0 = fmaxf(m0, __shfl_xor_sync(0xffffffffu, m0, 2));
        m1 = fmaxf(m1, __shfl_xor_sync(0xffffffffu, m1, 1));
        m1 = fmaxf(m1, __shfl_xor_sync(0xffffffffu, m1, 2));
        float mn0 = fmaxf(mrun0, m0), mn1 = fmaxf(mrun1, m1);
        float corr0 = __expf(mrun0 - mn0), corr1 = __expf(mrun1 - mn1);
        l0 *= corr0; l1 *= corr1;
        #pragma unroll
        for (int nt = 0; nt < 8; nt++) {
            o[nt][0] *= corr0; o[nt][1] *= corr0;
            o[nt][2] *= corr1; o[nt][3] *= corr1;
        }
        #pragma unroll
        for (int nt = 0; nt < 8; nt++) {
            float p0 = __expf(sc[nt][0] - mn0);
            float p1 = __expf(sc[nt][1] - mn0);
            float p2 = __expf(sc[nt][2] - mn1);
            float p3 = __expf(sc[nt][3] - mn1);
            l0 += p0 + p1; l1 += p2 + p3;
            unsigned* pp = prow + nt * 8 + 2 * fc;
            *(uint2*)pp = make_uint2(__float_as_uint(p0), __float_as_uint(p1));
            *(uint2*)(pp + 8 * ASTR) = make_uint2(__float_as_uint(p2), __float_as_uint(p3));
        }
        mrun0 = mn0; mrun1 = mn1;
        __syncwarp();

        // O += P @ V
        #pragma unroll
        for (int ks = 0; ks < 8; ks++) {
            unsigned a0, a1, a2, a3;
            ldsm4(a0, a1, a2, a3, qAddr + ((ks * 8) << 2));
            #pragma unroll
            for (int ntp = 0; ntp < 4; ntp++) {
                unsigned b0, b1, b2, b3;
                ldsm4(b0, b1, b2, b3, vAddr + ((ntp * 16 * ASTR + ks * 8) << 2));
                mma_tf32(o[2 * ntp + 0], a0, a1, a2, a3, b0, b1);
                mma_tf32(o[2 * ntp + 1], a0, a1, a2, a3, b2, b3);
            }
        }
        __syncwarp();   // PV reads done before next tile overwrites P/K/V
    }

    l0 += __shfl_xor_sync(0xffffffffu, l0, 1);
    l0 += __shfl_xor_sync(0xffffffffu, l0, 2);
    l1 += __shfl_xor_sync(0xffffffffu, l1, 1);
    l1 += __shfl_xor_sync(0xffffffffu, l1, 2);
    float inv0 = 1.f / l0, inv1 = 1.f / l1;

    int r0 = qt * 64 + w * 16 + fr;
    float* op0 = Op + (size_t)r0 * DMODEL;
    float* op1 = op0 + 8 * DMODEL;
    #pragma unroll
    for (int nt = 0; nt < 8; nt++) {
        int c = nt * 8 + 2 * fc;
        float2 v0; v0.x = o[nt][0] * inv0; v0.y = o[nt][1] * inv0;
        float2 v1; v1.x = o[nt][2] * inv1; v1.y = o[nt][3] * inv1;
        *(float2*)(op0 + c) = v0;
        *(float2*)(op1 + c) = v1;
    }
}

// ---------------- launch ----------------
extern "C" void kernel_launch(void* const* d_in, const int* in_sizes, int n_in,
                              void* d_out, int out_size)
{
    const float* x     = (const float*)d_in[0];
    const float* Wq    = (const float*)d_in[1];
    const float* Wk    = (const float*)d_in[2];
    const float* Wv    = (const float*)d_in[3];
    const float* Wo    = (const float*)d_in[4];
    const float* Wup   = (const float*)d_in[5];
    const float* Wdown = (const float*)d_in[6];
    const float* ln1m  = (const float*)d_in[7];
    const float* ln1s  = (const float*)d_in[8];
    const float* ln2m  = (const float*)d_in[9];
    const float* ln2s  = (const float*)d_in[10];
    float* out = (float*)d_out;

    float *ln, *q, *k, *v, *pre, *x1, *mid;
    cudaGetSymbolAddress((void**)&ln,  g_ln);
    cudaGetSymbolAddress((void**)&q,   g_q);
    cudaGetSymbolAddress((void**)&k,   g_k);
    cudaGetSymbolAddress((void**)&v,   g_v);
    cudaGetSymbolAddress((void**)&pre, g_pre);
    cudaGetSymbolAddress((void**)&x1,  g_x1);
    cudaGetSymbolAddress((void**)&mid, g_mid);

    cudaFuncSetAttribute(gemm_tf32_kernel<0>, cudaFuncAttributeMaxDynamicSharedMemorySize, GEMM_SMEM);
    cudaFuncSetAttribute(gemm_tf32_kernel<1>, cudaFuncAttributeMaxDynamicSharedMemorySize, GEMM_SMEM);
    cudaFuncSetAttribute(attn_mma_kernel,     cudaFuncAttributeMaxDynamicSharedMemorySize, ATT_SMEM);

    // LN1
    ln_kernel<<<MTOK, 256>>>(x, ln1m, ln1s, ln);

    // Q, K, V projections
    dim3 gD(DMODEL / 128, MTOK / 128);
    gemm_tf32_kernel<0><<<gD, 256, GEMM_SMEM>>>(ln, Wq, nullptr, q, MTOK, DMODEL, DMODEL);
    gemm_tf32_kernel<0><<<gD, 256, GEMM_SMEM>>>(ln, Wk, nullptr, k, MTOK, DMODEL, DMODEL);
    gemm_tf32_kernel<0><<<gD, 256, GEMM_SMEM>>>(ln, Wv, nullptr, v, MTOK, DMODEL, DMODEL);

    // causal flash attention (tensor cores)
    attn_mma_kernel<<<dim3(SEQ / 64, BATCH * NHEADS), 128, ATT_SMEM>>>(q, k, v, pre);

    // output projection + residual (x1 = x + attn_out)
    gemm_tf32_kernel<0><<<gD, 256, GEMM_SMEM>>>(pre, Wo, x, x1, MTOK, DMODEL, DMODEL);

    // LN2
    ln_kernel<<<MTOK, 256>>>(x1, ln2m, ln2s, ln);

    // MLP up + exact GELU
    dim3 gUp(DFF / 128, MTOK / 128);
    gemm_tf32_kernel<1><<<gUp, 256, GEMM_SMEM>>>(ln, Wup, nullptr, mid, MTOK, DFF, DMODEL);

    // MLP down + residual -> output
    gemm_tf32_kernel<0><<<gD, 256, GEMM_SMEM>>>(mid, Wdown, x1, out, MTOK, DMODEL, DFF);
}